// round 14
// baseline (speedup 1.0000x reference)
#include <cuda_runtime.h>
#include <cuda_bf16.h>
#include <cstdint>

#define B_SZ   8
#define SEQ    1024
#define CH     768
#define NHEAD  12
#define HDIM   64
#define QKV_LD (3*CH)
#define ATT_SCALE 0.125f

__device__ __nv_bfloat16 g_xh[(size_t)B_SZ * SEQ * CH];
__device__ __nv_bfloat16 g_xl[(size_t)B_SZ * SEQ * CH];
__device__ __nv_bfloat16 g_qh[(size_t)B_SZ * SEQ * QKV_LD];
__device__ __nv_bfloat16 g_ql[(size_t)B_SZ * SEQ * QKV_LD];
__device__ __nv_bfloat16 g_ath[(size_t)B_SZ * SEQ * CH];
__device__ __nv_bfloat16 g_atl[(size_t)B_SZ * SEQ * CH];
__device__ __nv_bfloat16 g_wqh[(size_t)QKV_LD * CH];
__device__ __nv_bfloat16 g_wql[(size_t)QKV_LD * CH];
__device__ __nv_bfloat16 g_wph[(size_t)CH * CH];
__device__ __nv_bfloat16 g_wpl[(size_t)CH * CH];

__device__ __forceinline__ uint32_t smem_u32(const void* p) {
    uint32_t a;
    asm("{ .reg .u64 t; cvta.to.shared.u64 t, %1; cvt.u32.u64 %0, t; }"
        : "=r"(a) : "l"(p));
    return a;
}
__device__ __forceinline__ void ldmatrix_x4(uint32_t* r, uint32_t addr) {
    asm volatile("ldmatrix.sync.aligned.m8n8.x4.shared.b16 {%0,%1,%2,%3}, [%4];"
                 : "=r"(r[0]), "=r"(r[1]), "=r"(r[2]), "=r"(r[3]) : "r"(addr));
}
__device__ __forceinline__ void ldmatrix_x4_trans(uint32_t* r, uint32_t addr) {
    asm volatile("ldmatrix.sync.aligned.m8n8.x4.trans.shared.b16 {%0,%1,%2,%3}, [%4];"
                 : "=r"(r[0]), "=r"(r[1]), "=r"(r[2]), "=r"(r[3]) : "r"(addr));
}
__device__ __forceinline__ void mma_bf16(float* d, const uint32_t* a,
                                         const uint32_t* b) {
    asm volatile(
        "mma.sync.aligned.m16n8k16.row.col.f32.bf16.bf16.f32 "
        "{%0,%1,%2,%3},{%4,%5,%6,%7},{%8,%9},{%0,%1,%2,%3};"
        : "+f"(d[0]), "+f"(d[1]), "+f"(d[2]), "+f"(d[3])
        : "r"(a[0]), "r"(a[1]), "r"(a[2]), "r"(a[3]), "r"(b[0]), "r"(b[1]));
}
__device__ __forceinline__ void cp16(uint32_t s, const void* g) {
    asm volatile("cp.async.cg.shared.global [%0], [%1], 16;" :: "r"(s), "l"(g));
}
__device__ __forceinline__ void cp_commit() {
    asm volatile("cp.async.commit_group;" ::: "memory");
}
__device__ __forceinline__ void cp_wait0() {
    asm volatile("cp.async.wait_group 0;" ::: "memory");
}
__device__ __forceinline__ uint32_t pack_bf2(__nv_bfloat16 a, __nv_bfloat16 b) {
    return (uint32_t)__bfloat16_as_ushort(a) |
           ((uint32_t)__bfloat16_as_ushort(b) << 16);
}
__device__ __forceinline__ void split_pack(float x, float y,
                                           uint32_t& hi, uint32_t& lo) {
    const __nv_bfloat16 hx = __float2bfloat16(x);
    const __nv_bfloat16 hy = __float2bfloat16(y);
    hi = pack_bf2(hx, hy);
    lo = pack_bf2(__float2bfloat16(x - __bfloat162float(hx)),
                  __float2bfloat16(y - __bfloat162float(hy)));
}

__global__ void split_kernel(const float* __restrict__ X,
                             __nv_bfloat16* __restrict__ Xh,
                             __nv_bfloat16* __restrict__ Xl)
{
    const size_t i = ((size_t)blockIdx.x * blockDim.x + threadIdx.x) * 4;
    const float4 v = *(const float4*)(X + i);
    uint32_t h0, l0, h1, l1;
    split_pack(v.x, v.y, h0, l0);
    split_pack(v.z, v.w, h1, l1);
    *(uint2*)(Xh + i) = make_uint2(h0, h1);
    *(uint2*)(Xl + i) = make_uint2(l0, l1);
}

__global__ void transpose_split_kernel(const float* __restrict__ W,
                                       __nv_bfloat16* __restrict__ Th,
                                       __nv_bfloat16* __restrict__ Tl,
                                       int K, int Nn)
{
    __shared__ float tile[32][33];
    const int n0 = blockIdx.x * 32;
    const int k0 = blockIdx.y * 32;
    const int tx = threadIdx.x;
    for (int i = threadIdx.y; i < 32; i += 8)
        tile[i][tx] = W[(size_t)(k0 + i) * Nn + n0 + tx];
    __syncthreads();
    for (int i = threadIdx.y; i < 32; i += 8) {
        const float v = tile[tx][i];
        const __nv_bfloat16 h = __float2bfloat16(v);
        const __nv_bfloat16 l = __float2bfloat16(v - __bfloat162float(h));
        const size_t o = (size_t)(n0 + i) * K + k0 + tx;
        Th[o] = h;
        Tl[o] = l;
    }
}

// ---------------------------------------------------------------------------
// All-bf16 split GEMM (unchanged from R13): CTA 128 x (NBG*32), BK=32,
// 2-stage cp.async. NBG=4 for QKV, NBG=3 for proj.
// ---------------------------------------------------------------------------
#define LDA 40
#define ARR_BYTES (128 * LDA * 2)
#define STAGE_BYTES (4 * ARR_BYTES)
#define GEMM_SMEM (2 * STAGE_BYTES)

template<int NBG>
__global__ __launch_bounds__(256) void gemm_bf16_kernel(
    const __nv_bfloat16* __restrict__ Ah, const __nv_bfloat16* __restrict__ Al,
    const __nv_bfloat16* __restrict__ Bh, const __nv_bfloat16* __restrict__ Bl,
    const float* __restrict__ bias, float* __restrict__ C,
    __nv_bfloat16* __restrict__ Chi, __nv_bfloat16* __restrict__ Clo,
    int M, int Nn, int K, int has_bias, int qcols)
{
    extern __shared__ __align__(16) char dsm[];
    const uint32_t sbase = smem_u32(dsm);

    const int tid  = threadIdx.x;
    const int wid  = tid >> 5;
    const int lane = tid & 31;
    const int wr   = wid >> 1;
    const int wc   = wid & 1;
    const int bm   = blockIdx.y * 128;
    const int bn   = blockIdx.x * (NBG * 32);

    const int r    = tid >> 1;
    const int half = tid & 1;
    const __nv_bfloat16* gAh = Ah + (size_t)(bm + r) * K + half * 16;
    const __nv_bfloat16* gAl = Al + (size_t)(bm + r) * K + half * 16;
    const __nv_bfloat16* gBh = Bh + (size_t)(bn + r) * K + half * 16;
    const __nv_bfloat16* gBl = Bl + (size_t)(bn + r) * K + half * 16;
    const uint32_t sOff = (uint32_t)(r * LDA + half * 16) * 2;
    const bool bld = (r < NBG * 32);

    const int lrow = lane & 15;
    const int lcol = (lane >> 4) << 3;

    float acc[2][2 * NBG][4];
#pragma unroll
    for (int a = 0; a < 2; a++)
#pragma unroll
        for (int b = 0; b < 2 * NBG; b++)
#pragma unroll
            for (int j = 0; j < 4; j++) acc[a][b][j] = 0.f;

    const int NIT = K / 32;

    {
        cp16(sbase + sOff,      gAh);  cp16(sbase + sOff + 16,      gAh + 8);
        cp16(sbase + ARR_BYTES + sOff,      gAl);
        cp16(sbase + ARR_BYTES + sOff + 16, gAl + 8);
        if (bld) {
            cp16(sbase + 2 * ARR_BYTES + sOff,      gBh);
            cp16(sbase + 2 * ARR_BYTES + sOff + 16, gBh + 8);
            cp16(sbase + 3 * ARR_BYTES + sOff,      gBl);
            cp16(sbase + 3 * ARR_BYTES + sOff + 16, gBl + 8);
        }
        cp_commit();
    }

    for (int it = 0; it < NIT; it++) {
        cp_wait0();
        __syncthreads();

        if (it + 1 < NIT) {
            const int k0 = (it + 1) * 32;
            const uint32_t us = sbase + ((it + 1) & 1) * STAGE_BYTES;
            cp16(us + sOff,      gAh + k0);  cp16(us + sOff + 16,      gAh + k0 + 8);
            cp16(us + ARR_BYTES + sOff,      gAl + k0);
            cp16(us + ARR_BYTES + sOff + 16, gAl + k0 + 8);
            if (bld) {
                cp16(us + 2 * ARR_BYTES + sOff,      gBh + k0);
                cp16(us + 2 * ARR_BYTES + sOff + 16, gBh + k0 + 8);
                cp16(us + 3 * ARR_BYTES + sOff,      gBl + k0);
                cp16(us + 3 * ARR_BYTES + sOff + 16, gBl + k0 + 8);
            }
            cp_commit();
        }

        const uint32_t uS  = sbase + (it & 1) * STAGE_BYTES;
        const uint32_t uAh = uS;
        const uint32_t uAl = uS + ARR_BYTES;
        const uint32_t uBh = uS + 2 * ARR_BYTES;
        const uint32_t uBl = uS + 3 * ARR_BYTES;

#pragma unroll
        for (int kk = 0; kk < 2; kk++) {
            const uint32_t cByte = (uint32_t)((kk * 16 + lcol) * 2);
            uint32_t ah[2][4], al[2][4];
#pragma unroll
            for (int a = 0; a < 2; a++) {
                const uint32_t ro =
                    (uint32_t)((wr * 32 + a * 16 + lrow) * (LDA * 2)) + cByte;
                ldmatrix_x4(ah[a], uAh + ro);
                ldmatrix_x4(al[a], uAl + ro);
            }
            uint32_t bh[2 * NBG][2], bl[2 * NBG][2];
#pragma unroll
            for (int g = 0; g < NBG; g++) {
                uint32_t t[4];
                const uint32_t ro =
                    (uint32_t)((wc * (NBG * 16) + g * 16 + lrow) * (LDA * 2)) + cByte;
                ldmatrix_x4(t, uBh + ro);
                bh[g * 2][0] = t[0]; bh[g * 2][1] = t[2];
                bh[g * 2 + 1][0] = t[1]; bh[g * 2 + 1][1] = t[3];
                ldmatrix_x4(t, uBl + ro);
                bl[g * 2][0] = t[0]; bl[g * 2][1] = t[2];
                bl[g * 2 + 1][0] = t[1]; bl[g * 2 + 1][1] = t[3];
            }
#pragma unroll
            for (int a = 0; a < 2; a++)
#pragma unroll
                for (int b = 0; b < 2 * NBG; b++) {
                    mma_bf16(acc[a][b], ah[a], bh[b]);
                    mma_bf16(acc[a][b], ah[a], bl[b]);
                    mma_bf16(acc[a][b], al[a], bh[b]);
                }
        }
        __syncthreads();
    }

    const int g  = lane >> 2;
    const int t2 = (lane & 3) * 2;
#pragma unroll
    for (int a = 0; a < 2; a++) {
        const int row0 = bm + wr * 32 + a * 16 + g;
#pragma unroll
        for (int b = 0; b < 2 * NBG; b++) {
            const int col = bn + wc * (NBG * 16) + b * 8 + t2;
            if (Chi) {
                const float sc = (col < qcols) ? ATT_SCALE : 1.f;
                uint32_t h0, l0, h1, l1;
                split_pack(acc[a][b][0] * sc, acc[a][b][1] * sc, h0, l0);
                split_pack(acc[a][b][2] * sc, acc[a][b][3] * sc, h1, l1);
                const size_t o0 = (size_t)row0 * Nn + col;
                const size_t o1 = (size_t)(row0 + 8) * Nn + col;
                *(uint32_t*)(Chi + o0) = h0;
                *(uint32_t*)(Clo + o0) = l0;
                *(uint32_t*)(Chi + o1) = h1;
                *(uint32_t*)(Clo + o1) = l1;
            } else {
                float bx = 0.f, by = 0.f;
                if (has_bias) { bx = bias[col]; by = bias[col + 1]; }
                *(float2*)(C + (size_t)row0 * Nn + col) =
                    make_float2(acc[a][b][0] + bx, acc[a][b][1] + by);
                *(float2*)(C + (size_t)(row0 + 8) * Nn + col) =
                    make_float2(acc[a][b][2] + bx, acc[a][b][3] + by);
            }
        }
    }
}

// ---------------------------------------------------------------------------
// Flash attention. R14: exp + row-sum accumulation interleaved into the PV
// ks loop (MUFU overlaps tensor); ps reduction + l update deferred to after.
// Summation order identical to R7/R13 -> bit-identical numerics.
// ---------------------------------------------------------------------------
#define KLD 72
#define FARR_BYTES (128 * KLD * 2)
#define FSTG_BYTES (4 * FARR_BYTES)
#define FLASH_SMEM (2 * FSTG_BYTES)

__global__ __launch_bounds__(256, 1) void flash_mma_kernel()
{
    extern __shared__ __align__(16) char fsm[];
    const uint32_t sbase = smem_u32(fsm);

    const int tid  = threadIdx.x;
    const int wid  = tid >> 5;
    const int lane = tid & 31;
    const int lrow = lane & 15;
    const int lcol = (lane >> 4) << 3;
    const int q0 = blockIdx.x * 128;
    const int b  = blockIdx.y / NHEAD;
    const int h  = blockIdx.y % NHEAD;

    const size_t tokbase = (size_t)b * SEQ;
    const __nv_bfloat16* qh_g = g_qh + tokbase * QKV_LD + h * HDIM;
    const __nv_bfloat16* ql_g = g_ql + tokbase * QKV_LD + h * HDIM;
    const __nv_bfloat16* kh_g = qh_g + CH;
    const __nv_bfloat16* kl_g = ql_g + CH;
    const __nv_bfloat16* vh_g = qh_g + 2 * CH;
    const __nv_bfloat16* vl_g = ql_g + 2 * CH;

    {
        __nv_bfloat16* Kh1 = (__nv_bfloat16*)(fsm + FSTG_BYTES);
        __nv_bfloat16* Kl1 = (__nv_bfloat16*)(fsm + FSTG_BYTES + FARR_BYTES);
        const int ldr = tid >> 1;
        const int ldh = (tid & 1) * 32;
        const __nv_bfloat16* sh = qh_g + (size_t)(q0 + ldr) * QKV_LD + ldh;
        const __nv_bfloat16* sl = ql_g + (size_t)(q0 + ldr) * QKV_LD + ldh;
#pragma unroll
        for (int i = 0; i < 4; i++) {
            *(uint4*)&Kh1[ldr * KLD + ldh + i * 8] = *(const uint4*)(sh + i * 8);
            *(uint4*)&Kl1[ldr * KLD + ldh + i * 8] = *(const uint4*)(sl + i * 8);
        }
    }
    __syncthreads();

    {
        const __nv_bfloat16* gsrc[4] = { kh_g, kl_g, vh_g, vl_g };
#pragma unroll
        for (int arr = 0; arr < 4; arr++)
#pragma unroll
            for (int c = 0; c < 4; c++) {
                const int ch  = tid + c * 256;
                const int row = ch >> 3;
                const int col = ch & 7;
                cp16(sbase + arr * FARR_BYTES + (uint32_t)(row * KLD + col * 8) * 2,
                     gsrc[arr] + (size_t)row * QKV_LD + col * 8);
            }
        cp_commit();
    }

    uint32_t qfh[4][4], qfl[4][4];
    {
        const uint32_t uQh = sbase + FSTG_BYTES;
        const uint32_t uQl = uQh + FARR_BYTES;
#pragma unroll
        for (int ks = 0; ks < 4; ks++) {
            const uint32_t ro =
                (uint32_t)((wid * 16 + lrow) * (KLD * 2)) + (ks * 16 + lcol) * 2;
            ldmatrix_x4(qfh[ks], uQh + ro);
            ldmatrix_x4(qfl[ks], uQl + ro);
        }
    }

    float m0 = -1e30f, m1 = -1e30f, l0 = 0.f, l1 = 0.f;
    float oacc[8][4];
#pragma unroll
    for (int j = 0; j < 8; j++)
#pragma unroll
        for (int c = 0; c < 4; c++) oacc[j][c] = 0.f;

    for (int t = 0; t < SEQ / 128; t++) {
        const int s = t & 1;
        cp_wait0();
        __syncthreads();

        if (t + 1 < SEQ / 128) {
            const int jn = (t + 1) * 128;
            const uint32_t us = sbase + (s ^ 1) * FSTG_BYTES;
            const __nv_bfloat16* gsrc[4] = { kh_g, kl_g, vh_g, vl_g };
#pragma unroll
            for (int arr = 0; arr < 4; arr++)
#pragma unroll
                for (int c = 0; c < 4; c++) {
                    const int ch  = tid + c * 256;
                    const int row = ch >> 3;
                    const int col = ch & 7;
                    cp16(us + arr * FARR_BYTES + (uint32_t)(row * KLD + col * 8) * 2,
                         gsrc[arr] + (size_t)(jn + row) * QKV_LD + col * 8);
                }
            cp_commit();
        }

        const uint32_t uS  = sbase + s * FSTG_BYTES;
        const uint32_t uKh = uS;
        const uint32_t uKl = uS + FARR_BYTES;
        const uint32_t uVh = uS + 2 * FARR_BYTES;
        const uint32_t uVl = uS + 3 * FARR_BYTES;

        // ---- S = Q @ K^T (3-term) ----
        float sacc[16][4];
#pragma unroll
        for (int j = 0; j < 16; j++)
#pragma unroll
            for (int c = 0; c < 4; c++) sacc[j][c] = 0.f;

#pragma unroll
        for (int ks = 0; ks < 4; ks++) {
            const uint32_t cByte = (uint32_t)((ks * 16 + lcol) * 2);
#pragma unroll
            for (int ng = 0; ng < 4; ng++) {
                uint32_t bh[4][2], bl[4][2], tt[4];
#pragma unroll
                for (int h2 = 0; h2 < 2; h2++) {
                    const uint32_t ro =
                        (uint32_t)((ng * 32 + h2 * 16 + lrow) * (KLD * 2)) + cByte;
                    ldmatrix_x4(tt, uKh + ro);
                    bh[h2 * 2][0] = tt[0]; bh[h2 * 2][1] = tt[2];
                    bh[h2 * 2 + 1][0] = tt[1]; bh[h2 * 2 + 1][1] = tt[3];
                    ldmatrix_x4(tt, uKl + ro);
                    bl[h2 * 2][0] = tt[0]; bl[h2 * 2][1] = tt[2];
                    bl[h2 * 2 + 1][0] = tt[1]; bl[h2 * 2 + 1][1] = tt[3];
                }
#pragma unroll
                for (int f = 0; f < 4; f++) {
                    float* d = sacc[ng * 4 + f];
                    mma_bf16(d, qfh[ks], bh[f]);
                    mma_bf16(d, qfh[ks], bl[f]);
                    mma_bf16(d, qfl[ks], bh[f]);
                }
            }
        }

        // ---- row max + correction ----
        float mx0 = sacc[0][0], mx1 = sacc[0][2];
#pragma unroll
        for (int j = 0; j < 16; j++) {
            mx0 = fmaxf(mx0, fmaxf(sacc[j][0], sacc[j][1]));
            mx1 = fmaxf(mx1, fmaxf(sacc[j][2], sacc[j][3]));
        }
        mx0 = fmaxf(mx0, __shfl_xor_sync(0xffffffffu, mx0, 1));
        mx0 = fmaxf(mx0, __shfl_xor_sync(0xffffffffu, mx0, 2));
        mx1 = fmaxf(mx1, __shfl_xor_sync(0xffffffffu, mx1, 1));
        mx1 = fmaxf(mx1, __shfl_xor_sync(0xffffffffu, mx1, 2));

        const float mn0 = fmaxf(m0, mx0);
        const float mn1 = fmaxf(m1, mx1);
        const float cr0 = __expf(m0 - mn0);
        const float cr1 = __expf(m1 - mn1);
        m0 = mn0; m1 = mn1;

#pragma unroll
        for (int j = 0; j < 8; j++) {
            oacc[j][0] *= cr0; oacc[j][1] *= cr0;
            oacc[j][2] *= cr1; oacc[j][3] *= cr1;
        }

        // ---- PV with exp/sum interleaved per ks (MUFU overlaps tensor) ----
        float ps0 = 0.f, ps1 = 0.f;
#pragma unroll
        for (int ks = 0; ks < 8; ks++) {
#pragma unroll
            for (int jj = 0; jj < 2; jj++) {
                const int j = 2 * ks + jj;
                sacc[j][0] = __expf(sacc[j][0] - mn0);
                sacc[j][1] = __expf(sacc[j][1] - mn0);
                sacc[j][2] = __expf(sacc[j][2] - mn1);
                sacc[j][3] = __expf(sacc[j][3] - mn1);
                ps0 += sacc[j][0] + sacc[j][1];
                ps1 += sacc[j][2] + sacc[j][3];
            }

            uint32_t pah[4], pal[4];
            split_pack(sacc[2 * ks][0], sacc[2 * ks][1], pah[0], pal[0]);
            split_pack(sacc[2 * ks][2], sacc[2 * ks][3], pah[1], pal[1]);
            split_pack(sacc[2 * ks + 1][0], sacc[2 * ks + 1][1], pah[2], pal[2]);
            split_pack(sacc[2 * ks + 1][2], sacc[2 * ks + 1][3], pah[3], pal[3]);

#pragma unroll
            for (int nd = 0; nd < 4; nd++) {
                const uint32_t ro =
                    (uint32_t)((ks * 16 + lrow) * (KLD * 2)) +
                    (uint32_t)((nd * 16 + lcol) * 2);
                uint32_t th[4], tl[4];
                ldmatrix_x4_trans(th, uVh + ro);
                ldmatrix_x4_trans(tl, uVl + ro);
#pragma unroll
                for (int f = 0; f < 2; f++) {
                    float* d = oacc[nd * 2 + f];
                    uint32_t vh2[2] = { th[f * 2], th[f * 2 + 1] };
                    uint32_t vl2[2] = { tl[f * 2], tl[f * 2 + 1] };
                    mma_bf16(d, pah, vh2);
                    mma_bf16(d, pah, vl2);
                    mma_bf16(d, pal, vh2);
                }
            }
        }

        // ---- deferred row-sum reduction + l update ----
        ps0 += __shfl_xor_sync(0xffffffffu, ps0, 1);
        ps0 += __shfl_xor_sync(0xffffffffu, ps0, 2);
        ps1 += __shfl_xor_sync(0xffffffffu, ps1, 1);
        ps1 += __shfl_xor_sync(0xffffffffu, ps1, 2);
        l0 = l0 * cr0 + ps0;
        l1 = l1 * cr1 + ps1;
    }

    const int g  = lane >> 2;
    const int t2 = (lane & 3) * 2;
    const float inv0 = 1.f / l0;
    const float inv1 = 1.f / l1;
    const int row0 = q0 + wid * 16 + g;
    __nv_bfloat16* oh = g_ath + (tokbase + row0) * CH + h * HDIM;
    __nv_bfloat16* ol = g_atl + (tokbase + row0) * CH + h * HDIM;
#pragma unroll
    for (int j = 0; j < 8; j++) {
        uint32_t hh, ll;
        split_pack(oacc[j][0] * inv0, oacc[j][1] * inv0, hh, ll);
        *(uint32_t*)(oh + j * 8 + t2) = hh;
        *(uint32_t*)(ol + j * 8 + t2) = ll;
        split_pack(oacc[j][2] * inv1, oacc[j][3] * inv1, hh, ll);
        *(uint32_t*)(oh + 8 * (size_t)CH + j * 8 + t2) = hh;
        *(uint32_t*)(ol + 8 * (size_t)CH + j * 8 + t2) = ll;
    }
}

// ---------------------------------------------------------------------------
extern "C" void kernel_launch(void* const* d_in, const int* in_sizes, int n_in,
                              void* d_out, int out_size)
{
    const float* x      = (const float*)d_in[0];
    const float* w_qkv  = (const float*)d_in[1];
    const float* w_proj = (const float*)d_in[2];
    const float* b_proj = (const float*)d_in[3];
    float* out = (float*)d_out;

    __nv_bfloat16 *xh, *xl, *qh, *ql, *ath, *atl, *wqh, *wql, *wph, *wpl;
    cudaGetSymbolAddress((void**)&xh, g_xh);
    cudaGetSymbolAddress((void**)&xl, g_xl);
    cudaGetSymbolAddress((void**)&qh, g_qh);
    cudaGetSymbolAddress((void**)&ql, g_ql);
    cudaGetSymbolAddress((void**)&ath, g_ath);
    cudaGetSymbolAddress((void**)&atl, g_atl);
    cudaGetSymbolAddress((void**)&wqh, g_wqh);
    cudaGetSymbolAddress((void**)&wql, g_wql);
    cudaGetSymbolAddress((void**)&wph, g_wph);
    cudaGetSymbolAddress((void**)&wpl, g_wpl);

    split_kernel<<<(B_SZ * SEQ * CH) / (256 * 4), 256>>>(x, xh, xl);
    transpose_split_kernel<<<dim3(QKV_LD / 32, CH / 32), dim3(32, 8)>>>(
        w_qkv, wqh, wql, CH, QKV_LD);
    transpose_split_kernel<<<dim3(CH / 32, CH / 32), dim3(32, 8)>>>(
        w_proj, wph, wpl, CH, CH);

    cudaFuncSetAttribute(gemm_bf16_kernel<4>,
                         cudaFuncAttributeMaxDynamicSharedMemorySize, GEMM_SMEM);
    gemm_bf16_kernel<4><<<dim3(QKV_LD / 128, (B_SZ * SEQ) / 128), 256, GEMM_SMEM>>>(
        xh, xl, wqh, wql, nullptr, nullptr, qh, ql,
        B_SZ * SEQ, QKV_LD, CH, 0, CH);

    cudaFuncSetAttribute(flash_mma_kernel,
                         cudaFuncAttributeMaxDynamicSharedMemorySize, FLASH_SMEM);
    flash_mma_kernel<<<dim3(SEQ / 128, B_SZ * NHEAD), 256, FLASH_SMEM>>>();

    cudaFuncSetAttribute(gemm_bf16_kernel<3>,
                         cudaFuncAttributeMaxDynamicSharedMemorySize, GEMM_SMEM);
    gemm_bf16_kernel<3><<<dim3(CH / 96, (B_SZ * SEQ) / 128), 256, GEMM_SMEM>>>(
        ath, atl, wph, wpl, b_proj, out, nullptr, nullptr,
        B_SZ * SEQ, CH, CH, 1, 0);
}

// round 15
// speedup vs baseline: 1.0048x; 1.0048x over previous
#include <cuda_runtime.h>
#include <cuda_bf16.h>
#include <cstdint>

#define B_SZ   8
#define SEQ    1024
#define CH     768
#define NHEAD  12
#define HDIM   64
#define QKV_LD (3*CH)
#define ATT_SCALE 0.125f

__device__ __nv_bfloat16 g_xh[(size_t)B_SZ * SEQ * CH];
__device__ __nv_bfloat16 g_xl[(size_t)B_SZ * SEQ * CH];
__device__ __nv_bfloat16 g_qh[(size_t)B_SZ * SEQ * QKV_LD];
__device__ __nv_bfloat16 g_ql[(size_t)B_SZ * SEQ * QKV_LD];
__device__ __nv_bfloat16 g_ath[(size_t)B_SZ * SEQ * CH];
__device__ __nv_bfloat16 g_atl[(size_t)B_SZ * SEQ * CH];
__device__ __nv_bfloat16 g_wqh[(size_t)QKV_LD * CH];
__device__ __nv_bfloat16 g_wql[(size_t)QKV_LD * CH];
__device__ __nv_bfloat16 g_wph[(size_t)CH * CH];
__device__ __nv_bfloat16 g_wpl[(size_t)CH * CH];

__device__ __forceinline__ uint32_t smem_u32(const void* p) {
    uint32_t a;
    asm("{ .reg .u64 t; cvta.to.shared.u64 t, %1; cvt.u32.u64 %0, t; }"
        : "=r"(a) : "l"(p));
    return a;
}
__device__ __forceinline__ void ldmatrix_x4(uint32_t* r, uint32_t addr) {
    asm volatile("ldmatrix.sync.aligned.m8n8.x4.shared.b16 {%0,%1,%2,%3}, [%4];"
                 : "=r"(r[0]), "=r"(r[1]), "=r"(r[2]), "=r"(r[3]) : "r"(addr));
}
__device__ __forceinline__ void ldmatrix_x4_trans(uint32_t* r, uint32_t addr) {
    asm volatile("ldmatrix.sync.aligned.m8n8.x4.trans.shared.b16 {%0,%1,%2,%3}, [%4];"
                 : "=r"(r[0]), "=r"(r[1]), "=r"(r[2]), "=r"(r[3]) : "r"(addr));
}
__device__ __forceinline__ void mma_bf16(float* d, const uint32_t* a,
                                         const uint32_t* b) {
    asm volatile(
        "mma.sync.aligned.m16n8k16.row.col.f32.bf16.bf16.f32 "
        "{%0,%1,%2,%3},{%4,%5,%6,%7},{%8,%9},{%0,%1,%2,%3};"
        : "+f"(d[0]), "+f"(d[1]), "+f"(d[2]), "+f"(d[3])
        : "r"(a[0]), "r"(a[1]), "r"(a[2]), "r"(a[3]), "r"(b[0]), "r"(b[1]));
}
__device__ __forceinline__ void cp16(uint32_t s, const void* g) {
    asm volatile("cp.async.cg.shared.global [%0], [%1], 16;" :: "r"(s), "l"(g));
}
__device__ __forceinline__ void cp_commit() {
    asm volatile("cp.async.commit_group;" ::: "memory");
}
__device__ __forceinline__ void cp_wait0() {
    asm volatile("cp.async.wait_group 0;" ::: "memory");
}
__device__ __forceinline__ uint32_t pack_bf2(__nv_bfloat16 a, __nv_bfloat16 b) {
    return (uint32_t)__bfloat16_as_ushort(a) |
           ((uint32_t)__bfloat16_as_ushort(b) << 16);
}
__device__ __forceinline__ void split_pack(float x, float y,
                                           uint32_t& hi, uint32_t& lo) {
    const __nv_bfloat16 hx = __float2bfloat16(x);
    const __nv_bfloat16 hy = __float2bfloat16(y);
    hi = pack_bf2(hx, hy);
    lo = pack_bf2(__float2bfloat16(x - __bfloat162float(hx)),
                  __float2bfloat16(y - __bfloat162float(hy)));
}

// ---------------------------------------------------------------------------
// Fused prep: one launch covers x split + both weight transpose/splits.
// Region A: blocks [0, NBLK_X)                 — x fp32 -> xh/xl
// Region B: blocks [NBLK_X, NBLK_X+NBLK_WQ)    — w_qkv  -> wqh/wql [N,K]
// Region C: blocks [.., +NBLK_WP)              — w_proj -> wph/wpl [N,K]
// ---------------------------------------------------------------------------
#define NBLK_X  ((B_SZ * SEQ * CH) / (256 * 4))      /* 6144 */
#define NBLK_WQ ((QKV_LD / 32) * (CH / 32))          /* 1728 */
#define NBLK_WP ((CH / 32) * (CH / 32))              /* 576  */

__device__ __forceinline__ void transpose_split_body(
    const float* __restrict__ W, __nv_bfloat16* __restrict__ Th,
    __nv_bfloat16* __restrict__ Tl, int K, int Nn, int bx, int by, int tid)
{
    __shared__ float tile[32][33];
    const int n0 = bx * 32;
    const int k0 = by * 32;
    const int tx = tid & 31;
    const int ty = tid >> 5;           // 0..7
    for (int i = ty; i < 32; i += 8)
        tile[i][tx] = W[(size_t)(k0 + i) * Nn + n0 + tx];
    __syncthreads();
    for (int i = ty; i < 32; i += 8) {
        const float v = tile[tx][i];
        const __nv_bfloat16 h = __float2bfloat16(v);
        const __nv_bfloat16 l = __float2bfloat16(v - __bfloat162float(h));
        const size_t o = (size_t)(n0 + i) * K + k0 + tx;
        Th[o] = h;
        Tl[o] = l;
    }
}

__global__ __launch_bounds__(256) void prep_kernel(
    const float* __restrict__ X,
    const float* __restrict__ Wq, const float* __restrict__ Wp)
{
    const int bid = blockIdx.x;
    if (bid < NBLK_X) {
        const size_t i = ((size_t)bid * 256 + threadIdx.x) * 4;
        const float4 v = *(const float4*)(X + i);
        uint32_t h0, l0, h1, l1;
        split_pack(v.x, v.y, h0, l0);
        split_pack(v.z, v.w, h1, l1);
        *(uint2*)(g_xh + i) = make_uint2(h0, h1);
        *(uint2*)(g_xl + i) = make_uint2(l0, l1);
    } else if (bid < NBLK_X + NBLK_WQ) {
        const int tb = bid - NBLK_X;
        transpose_split_body(Wq, g_wqh, g_wql, CH, QKV_LD,
                             tb % (QKV_LD / 32), tb / (QKV_LD / 32),
                             threadIdx.x);
    } else {
        const int tb = bid - NBLK_X - NBLK_WQ;
        transpose_split_body(Wp, g_wph, g_wpl, CH, CH,
                             tb % (CH / 32), tb / (CH / 32),
                             threadIdx.x);
    }
}

// ---------------------------------------------------------------------------
// All-bf16 split GEMM (unchanged from R13): CTA 128 x (NBG*32), BK=32,
// 2-stage cp.async. NBG=4 for QKV, NBG=3 for proj.
// ---------------------------------------------------------------------------
#define LDA 40
#define ARR_BYTES (128 * LDA * 2)
#define STAGE_BYTES (4 * ARR_BYTES)
#define GEMM_SMEM (2 * STAGE_BYTES)

template<int NBG>
__global__ __launch_bounds__(256) void gemm_bf16_kernel(
    const __nv_bfloat16* __restrict__ Ah, const __nv_bfloat16* __restrict__ Al,
    const __nv_bfloat16* __restrict__ Bh, const __nv_bfloat16* __restrict__ Bl,
    const float* __restrict__ bias, float* __restrict__ C,
    __nv_bfloat16* __restrict__ Chi, __nv_bfloat16* __restrict__ Clo,
    int M, int Nn, int K, int has_bias, int qcols)
{
    extern __shared__ __align__(16) char dsm[];
    const uint32_t sbase = smem_u32(dsm);

    const int tid  = threadIdx.x;
    const int wid  = tid >> 5;
    const int lane = tid & 31;
    const int wr   = wid >> 1;
    const int wc   = wid & 1;
    const int bm   = blockIdx.y * 128;
    const int bn   = blockIdx.x * (NBG * 32);

    const int r    = tid >> 1;
    const int half = tid & 1;
    const __nv_bfloat16* gAh = Ah + (size_t)(bm + r) * K + half * 16;
    const __nv_bfloat16* gAl = Al + (size_t)(bm + r) * K + half * 16;
    const __nv_bfloat16* gBh = Bh + (size_t)(bn + r) * K + half * 16;
    const __nv_bfloat16* gBl = Bl + (size_t)(bn + r) * K + half * 16;
    const uint32_t sOff = (uint32_t)(r * LDA + half * 16) * 2;
    const bool bld = (r < NBG * 32);

    const int lrow = lane & 15;
    const int lcol = (lane >> 4) << 3;

    float acc[2][2 * NBG][4];
#pragma unroll
    for (int a = 0; a < 2; a++)
#pragma unroll
        for (int b = 0; b < 2 * NBG; b++)
#pragma unroll
            for (int j = 0; j < 4; j++) acc[a][b][j] = 0.f;

    const int NIT = K / 32;

    {
        cp16(sbase + sOff,      gAh);  cp16(sbase + sOff + 16,      gAh + 8);
        cp16(sbase + ARR_BYTES + sOff,      gAl);
        cp16(sbase + ARR_BYTES + sOff + 16, gAl + 8);
        if (bld) {
            cp16(sbase + 2 * ARR_BYTES + sOff,      gBh);
            cp16(sbase + 2 * ARR_BYTES + sOff + 16, gBh + 8);
            cp16(sbase + 3 * ARR_BYTES + sOff,      gBl);
            cp16(sbase + 3 * ARR_BYTES + sOff + 16, gBl + 8);
        }
        cp_commit();
    }

    for (int it = 0; it < NIT; it++) {
        cp_wait0();
        __syncthreads();

        if (it + 1 < NIT) {
            const int k0 = (it + 1) * 32;
            const uint32_t us = sbase + ((it + 1) & 1) * STAGE_BYTES;
            cp16(us + sOff,      gAh + k0);  cp16(us + sOff + 16,      gAh + k0 + 8);
            cp16(us + ARR_BYTES + sOff,      gAl + k0);
            cp16(us + ARR_BYTES + sOff + 16, gAl + k0 + 8);
            if (bld) {
                cp16(us + 2 * ARR_BYTES + sOff,      gBh + k0);
                cp16(us + 2 * ARR_BYTES + sOff + 16, gBh + k0 + 8);
                cp16(us + 3 * ARR_BYTES + sOff,      gBl + k0);
                cp16(us + 3 * ARR_BYTES + sOff + 16, gBl + k0 + 8);
            }
            cp_commit();
        }

        const uint32_t uS  = sbase + (it & 1) * STAGE_BYTES;
        const uint32_t uAh = uS;
        const uint32_t uAl = uS + ARR_BYTES;
        const uint32_t uBh = uS + 2 * ARR_BYTES;
        const uint32_t uBl = uS + 3 * ARR_BYTES;

#pragma unroll
        for (int kk = 0; kk < 2; kk++) {
            const uint32_t cByte = (uint32_t)((kk * 16 + lcol) * 2);
            uint32_t ah[2][4], al[2][4];
#pragma unroll
            for (int a = 0; a < 2; a++) {
                const uint32_t ro =
                    (uint32_t)((wr * 32 + a * 16 + lrow) * (LDA * 2)) + cByte;
                ldmatrix_x4(ah[a], uAh + ro);
                ldmatrix_x4(al[a], uAl + ro);
            }
            uint32_t bh[2 * NBG][2], bl[2 * NBG][2];
#pragma unroll
            for (int g = 0; g < NBG; g++) {
                uint32_t t[4];
                const uint32_t ro =
                    (uint32_t)((wc * (NBG * 16) + g * 16 + lrow) * (LDA * 2)) + cByte;
                ldmatrix_x4(t, uBh + ro);
                bh[g * 2][0] = t[0]; bh[g * 2][1] = t[2];
                bh[g * 2 + 1][0] = t[1]; bh[g * 2 + 1][1] = t[3];
                ldmatrix_x4(t, uBl + ro);
                bl[g * 2][0] = t[0]; bl[g * 2][1] = t[2];
                bl[g * 2 + 1][0] = t[1]; bl[g * 2 + 1][1] = t[3];
            }
#pragma unroll
            for (int a = 0; a < 2; a++)
#pragma unroll
                for (int b = 0; b < 2 * NBG; b++) {
                    mma_bf16(acc[a][b], ah[a], bh[b]);
                    mma_bf16(acc[a][b], ah[a], bl[b]);
                    mma_bf16(acc[a][b], al[a], bh[b]);
                }
        }
        __syncthreads();
    }

    const int g  = lane >> 2;
    const int t2 = (lane & 3) * 2;
#pragma unroll
    for (int a = 0; a < 2; a++) {
        const int row0 = bm + wr * 32 + a * 16 + g;
#pragma unroll
        for (int b = 0; b < 2 * NBG; b++) {
            const int col = bn + wc * (NBG * 16) + b * 8 + t2;
            if (Chi) {
                const float sc = (col < qcols) ? ATT_SCALE : 1.f;
                uint32_t h0, l0, h1, l1;
                split_pack(acc[a][b][0] * sc, acc[a][b][1] * sc, h0, l0);
                split_pack(acc[a][b][2] * sc, acc[a][b][3] * sc, h1, l1);
                const size_t o0 = (size_t)row0 * Nn + col;
                const size_t o1 = (size_t)(row0 + 8) * Nn + col;
                *(uint32_t*)(Chi + o0) = h0;
                *(uint32_t*)(Clo + o0) = l0;
                *(uint32_t*)(Chi + o1) = h1;
                *(uint32_t*)(Clo + o1) = l1;
            } else {
                float bx = 0.f, by = 0.f;
                if (has_bias) { bx = bias[col]; by = bias[col + 1]; }
                *(float2*)(C + (size_t)row0 * Nn + col) =
                    make_float2(acc[a][b][0] + bx, acc[a][b][1] + by);
                *(float2*)(C + (size_t)(row0 + 8) * Nn + col) =
                    make_float2(acc[a][b][2] + bx, acc[a][b][3] + by);
            }
        }
    }
}

// ---------------------------------------------------------------------------
// Flash attention (R14 version — exp interleaved with PV, unchanged timing)
// ---------------------------------------------------------------------------
#define KLD 72
#define FARR_BYTES (128 * KLD * 2)
#define FSTG_BYTES (4 * FARR_BYTES)
#define FLASH_SMEM (2 * FSTG_BYTES)

__global__ __launch_bounds__(256, 1) void flash_mma_kernel()
{
    extern __shared__ __align__(16) char fsm[];
    const uint32_t sbase = smem_u32(fsm);

    const int tid  = threadIdx.x;
    const int wid  = tid >> 5;
    const int lane = tid & 31;
    const int lrow = lane & 15;
    const int lcol = (lane >> 4) << 3;
    const int q0 = blockIdx.x * 128;
    const int b  = blockIdx.y / NHEAD;
    const int h  = blockIdx.y % NHEAD;

    const size_t tokbase = (size_t)b * SEQ;
    const __nv_bfloat16* qh_g = g_qh + tokbase * QKV_LD + h * HDIM;
    const __nv_bfloat16* ql_g = g_ql + tokbase * QKV_LD + h * HDIM;
    const __nv_bfloat16* kh_g = qh_g + CH;
    const __nv_bfloat16* kl_g = ql_g + CH;
    const __nv_bfloat16* vh_g = qh_g + 2 * CH;
    const __nv_bfloat16* vl_g = ql_g + 2 * CH;

    {
        __nv_bfloat16* Kh1 = (__nv_bfloat16*)(fsm + FSTG_BYTES);
        __nv_bfloat16* Kl1 = (__nv_bfloat16*)(fsm + FSTG_BYTES + FARR_BYTES);
        const int ldr = tid >> 1;
        const int ldh = (tid & 1) * 32;
        const __nv_bfloat16* sh = qh_g + (size_t)(q0 + ldr) * QKV_LD + ldh;
        const __nv_bfloat16* sl = ql_g + (size_t)(q0 + ldr) * QKV_LD + ldh;
#pragma unroll
        for (int i = 0; i < 4; i++) {
            *(uint4*)&Kh1[ldr * KLD + ldh + i * 8] = *(const uint4*)(sh + i * 8);
            *(uint4*)&Kl1[ldr * KLD + ldh + i * 8] = *(const uint4*)(sl + i * 8);
        }
    }
    __syncthreads();

    {
        const __nv_bfloat16* gsrc[4] = { kh_g, kl_g, vh_g, vl_g };
#pragma unroll
        for (int arr = 0; arr < 4; arr++)
#pragma unroll
            for (int c = 0; c < 4; c++) {
                const int ch  = tid + c * 256;
                const int row = ch >> 3;
                const int col = ch & 7;
                cp16(sbase + arr * FARR_BYTES + (uint32_t)(row * KLD + col * 8) * 2,
                     gsrc[arr] + (size_t)row * QKV_LD + col * 8);
            }
        cp_commit();
    }

    uint32_t qfh[4][4], qfl[4][4];
    {
        const uint32_t uQh = sbase + FSTG_BYTES;
        const uint32_t uQl = uQh + FARR_BYTES;
#pragma unroll
        for (int ks = 0; ks < 4; ks++) {
            const uint32_t ro =
                (uint32_t)((wid * 16 + lrow) * (KLD * 2)) + (ks * 16 + lcol) * 2;
            ldmatrix_x4(qfh[ks], uQh + ro);
            ldmatrix_x4(qfl[ks], uQl + ro);
        }
    }

    float m0 = -1e30f, m1 = -1e30f, l0 = 0.f, l1 = 0.f;
    float oacc[8][4];
#pragma unroll
    for (int j = 0; j < 8; j++)
#pragma unroll
        for (int c = 0; c < 4; c++) oacc[j][c] = 0.f;

    for (int t = 0; t < SEQ / 128; t++) {
        const int s = t & 1;
        cp_wait0();
        __syncthreads();

        if (t + 1 < SEQ / 128) {
            const int jn = (t + 1) * 128;
            const uint32_t us = sbase + (s ^ 1) * FSTG_BYTES;
            const __nv_bfloat16* gsrc[4] = { kh_g, kl_g, vh_g, vl_g };
#pragma unroll
            for (int arr = 0; arr < 4; arr++)
#pragma unroll
                for (int c = 0; c < 4; c++) {
                    const int ch  = tid + c * 256;
                    const int row = ch >> 3;
                    const int col = ch & 7;
                    cp16(us + arr * FARR_BYTES + (uint32_t)(row * KLD + col * 8) * 2,
                         gsrc[arr] + (size_t)(jn + row) * QKV_LD + col * 8);
                }
            cp_commit();
        }

        const uint32_t uS  = sbase + s * FSTG_BYTES;
        const uint32_t uKh = uS;
        const uint32_t uKl = uS + FARR_BYTES;
        const uint32_t uVh = uS + 2 * FARR_BYTES;
        const uint32_t uVl = uS + 3 * FARR_BYTES;

        float sacc[16][4];
#pragma unroll
        for (int j = 0; j < 16; j++)
#pragma unroll
            for (int c = 0; c < 4; c++) sacc[j][c] = 0.f;

#pragma unroll
        for (int ks = 0; ks < 4; ks++) {
            const uint32_t cByte = (uint32_t)((ks * 16 + lcol) * 2);
#pragma unroll
            for (int ng = 0; ng < 4; ng++) {
                uint32_t bh[4][2], bl[4][2], tt[4];
#pragma unroll
                for (int h2 = 0; h2 < 2; h2++) {
                    const uint32_t ro =
                        (uint32_t)((ng * 32 + h2 * 16 + lrow) * (KLD * 2)) + cByte;
                    ldmatrix_x4(tt, uKh + ro);
                    bh[h2 * 2][0] = tt[0]; bh[h2 * 2][1] = tt[2];
                    bh[h2 * 2 + 1][0] = tt[1]; bh[h2 * 2 + 1][1] = tt[3];
                    ldmatrix_x4(tt, uKl + ro);
                    bl[h2 * 2][0] = tt[0]; bl[h2 * 2][1] = tt[2];
                    bl[h2 * 2 + 1][0] = tt[1]; bl[h2 * 2 + 1][1] = tt[3];
                }
#pragma unroll
                for (int f = 0; f < 4; f++) {
                    float* d = sacc[ng * 4 + f];
                    mma_bf16(d, qfh[ks], bh[f]);
                    mma_bf16(d, qfh[ks], bl[f]);
                    mma_bf16(d, qfl[ks], bh[f]);
                }
            }
        }

        float mx0 = sacc[0][0], mx1 = sacc[0][2];
#pragma unroll
        for (int j = 0; j < 16; j++) {
            mx0 = fmaxf(mx0, fmaxf(sacc[j][0], sacc[j][1]));
            mx1 = fmaxf(mx1, fmaxf(sacc[j][2], sacc[j][3]));
        }
        mx0 = fmaxf(mx0, __shfl_xor_sync(0xffffffffu, mx0, 1));
        mx0 = fmaxf(mx0, __shfl_xor_sync(0xffffffffu, mx0, 2));
        mx1 = fmaxf(mx1, __shfl_xor_sync(0xffffffffu, mx1, 1));
        mx1 = fmaxf(mx1, __shfl_xor_sync(0xffffffffu, mx1, 2));

        const float mn0 = fmaxf(m0, mx0);
        const float mn1 = fmaxf(m1, mx1);
        const float cr0 = __expf(m0 - mn0);
        const float cr1 = __expf(m1 - mn1);
        m0 = mn0; m1 = mn1;

#pragma unroll
        for (int j = 0; j < 8; j++) {
            oacc[j][0] *= cr0; oacc[j][1] *= cr0;
            oacc[j][2] *= cr1; oacc[j][3] *= cr1;
        }

        float ps0 = 0.f, ps1 = 0.f;
#pragma unroll
        for (int ks = 0; ks < 8; ks++) {
#pragma unroll
            for (int jj = 0; jj < 2; jj++) {
                const int j = 2 * ks + jj;
                sacc[j][0] = __expf(sacc[j][0] - mn0);
                sacc[j][1] = __expf(sacc[j][1] - mn0);
                sacc[j][2] = __expf(sacc[j][2] - mn1);
                sacc[j][3] = __expf(sacc[j][3] - mn1);
                ps0 += sacc[j][0] + sacc[j][1];
                ps1 += sacc[j][2] + sacc[j][3];
            }

            uint32_t pah[4], pal[4];
            split_pack(sacc[2 * ks][0], sacc[2 * ks][1], pah[0], pal[0]);
            split_pack(sacc[2 * ks][2], sacc[2 * ks][3], pah[1], pal[1]);
            split_pack(sacc[2 * ks + 1][0], sacc[2 * ks + 1][1], pah[2], pal[2]);
            split_pack(sacc[2 * ks + 1][2], sacc[2 * ks + 1][3], pah[3], pal[3]);

#pragma unroll
            for (int nd = 0; nd < 4; nd++) {
                const uint32_t ro =
                    (uint32_t)((ks * 16 + lrow) * (KLD * 2)) +
                    (uint32_t)((nd * 16 + lcol) * 2);
                uint32_t th[4], tl[4];
                ldmatrix_x4_trans(th, uVh + ro);
                ldmatrix_x4_trans(tl, uVl + ro);
#pragma unroll
                for (int f = 0; f < 2; f++) {
                    float* d = oacc[nd * 2 + f];
                    uint32_t vh2[2] = { th[f * 2], th[f * 2 + 1] };
                    uint32_t vl2[2] = { tl[f * 2], tl[f * 2 + 1] };
                    mma_bf16(d, pah, vh2);
                    mma_bf16(d, pah, vl2);
                    mma_bf16(d, pal, vh2);
                }
            }
        }

        ps0 += __shfl_xor_sync(0xffffffffu, ps0, 1);
        ps0 += __shfl_xor_sync(0xffffffffu, ps0, 2);
        ps1 += __shfl_xor_sync(0xffffffffu, ps1, 1);
        ps1 += __shfl_xor_sync(0xffffffffu, ps1, 2);
        l0 = l0 * cr0 + ps0;
        l1 = l1 * cr1 + ps1;
    }

    const int g  = lane >> 2;
    const int t2 = (lane & 3) * 2;
    const float inv0 = 1.f / l0;
    const float inv1 = 1.f / l1;
    const int row0 = q0 + wid * 16 + g;
    __nv_bfloat16* oh = g_ath + (tokbase + row0) * CH + h * HDIM;
    __nv_bfloat16* ol = g_atl + (tokbase + row0) * CH + h * HDIM;
#pragma unroll
    for (int j = 0; j < 8; j++) {
        uint32_t hh, ll;
        split_pack(oacc[j][0] * inv0, oacc[j][1] * inv0, hh, ll);
        *(uint32_t*)(oh + j * 8 + t2) = hh;
        *(uint32_t*)(ol + j * 8 + t2) = ll;
        split_pack(oacc[j][2] * inv1, oacc[j][3] * inv1, hh, ll);
        *(uint32_t*)(oh + 8 * (size_t)CH + j * 8 + t2) = hh;
        *(uint32_t*)(ol + 8 * (size_t)CH + j * 8 + t2) = ll;
    }
}

// ---------------------------------------------------------------------------
extern "C" void kernel_launch(void* const* d_in, const int* in_sizes, int n_in,
                              void* d_out, int out_size)
{
    const float* x      = (const float*)d_in[0];
    const float* w_qkv  = (const float*)d_in[1];
    const float* w_proj = (const float*)d_in[2];
    const float* b_proj = (const float*)d_in[3];
    float* out = (float*)d_out;

    __nv_bfloat16 *xh, *xl, *qh, *ql, *ath, *atl, *wqh, *wql, *wph, *wpl;
    cudaGetSymbolAddress((void**)&xh, g_xh);
    cudaGetSymbolAddress((void**)&xl, g_xl);
    cudaGetSymbolAddress((void**)&qh, g_qh);
    cudaGetSymbolAddress((void**)&ql, g_ql);
    cudaGetSymbolAddress((void**)&ath, g_ath);
    cudaGetSymbolAddress((void**)&atl, g_atl);
    cudaGetSymbolAddress((void**)&wqh, g_wqh);
    cudaGetSymbolAddress((void**)&wql, g_wql);
    cudaGetSymbolAddress((void**)&wph, g_wph);
    cudaGetSymbolAddress((void**)&wpl, g_wpl);

    // 0) Fused prep: x split + both weight transpose/splits in one launch
    prep_kernel<<<NBLK_X + NBLK_WQ + NBLK_WP, 256>>>(x, w_qkv, w_proj);

    // 1) QKV projection: 128-wide N tiles
    cudaFuncSetAttribute(gemm_bf16_kernel<4>,
                         cudaFuncAttributeMaxDynamicSharedMemorySize, GEMM_SMEM);
    gemm_bf16_kernel<4><<<dim3(QKV_LD / 128, (B_SZ * SEQ) / 128), 256, GEMM_SMEM>>>(
        xh, xl, wqh, wql, nullptr, nullptr, qh, ql,
        B_SZ * SEQ, QKV_LD, CH, 0, CH);

    // 2) Flash attention
    cudaFuncSetAttribute(flash_mma_kernel,
                         cudaFuncAttributeMaxDynamicSharedMemorySize, FLASH_SMEM);
    flash_mma_kernel<<<dim3(SEQ / 128, B_SZ * NHEAD), 256, FLASH_SMEM>>>();

    // 3) Output projection: 96-wide N tiles
    cudaFuncSetAttribute(gemm_bf16_kernel<3>,
                         cudaFuncAttributeMaxDynamicSharedMemorySize, GEMM_SMEM);
    gemm_bf16_kernel<3><<<dim3(CH / 96, (B_SZ * SEQ) / 128), 256, GEMM_SMEM>>>(
        ath, atl, wph, wpl, b_proj, out, nullptr, nullptr,
        B_SZ * SEQ, CH, CH, 1, 0);
}

// round 16
// speedup vs baseline: 1.0084x; 1.0036x over previous
#include <cuda_runtime.h>
#include <cuda_bf16.h>
#include <cstdint>

#define B_SZ   8
#define SEQ    1024
#define CH     768
#define NHEAD  12
#define HDIM   64
#define QKV_LD (3*CH)
#define ATT_SCALE 0.125f

__device__ __nv_bfloat16 g_xh[(size_t)B_SZ * SEQ * CH];
__device__ __nv_bfloat16 g_xl[(size_t)B_SZ * SEQ * CH];
__device__ __nv_bfloat16 g_qh[(size_t)B_SZ * SEQ * QKV_LD];
__device__ __nv_bfloat16 g_ql[(size_t)B_SZ * SEQ * QKV_LD];
__device__ __nv_bfloat16 g_ath[(size_t)B_SZ * SEQ * CH];
__device__ __nv_bfloat16 g_atl[(size_t)B_SZ * SEQ * CH];
__device__ __nv_bfloat16 g_wqh[(size_t)QKV_LD * CH];
__device__ __nv_bfloat16 g_wql[(size_t)QKV_LD * CH];
__device__ __nv_bfloat16 g_wph[(size_t)CH * CH];
__device__ __nv_bfloat16 g_wpl[(size_t)CH * CH];

__device__ __forceinline__ uint32_t smem_u32(const void* p) {
    uint32_t a;
    asm("{ .reg .u64 t; cvta.to.shared.u64 t, %1; cvt.u32.u64 %0, t; }"
        : "=r"(a) : "l"(p));
    return a;
}
__device__ __forceinline__ void ldmatrix_x4(uint32_t* r, uint32_t addr) {
    asm volatile("ldmatrix.sync.aligned.m8n8.x4.shared.b16 {%0,%1,%2,%3}, [%4];"
                 : "=r"(r[0]), "=r"(r[1]), "=r"(r[2]), "=r"(r[3]) : "r"(addr));
}
__device__ __forceinline__ void ldmatrix_x4_trans(uint32_t* r, uint32_t addr) {
    asm volatile("ldmatrix.sync.aligned.m8n8.x4.trans.shared.b16 {%0,%1,%2,%3}, [%4];"
                 : "=r"(r[0]), "=r"(r[1]), "=r"(r[2]), "=r"(r[3]) : "r"(addr));
}
__device__ __forceinline__ void mma_bf16(float* d, const uint32_t* a,
                                         const uint32_t* b) {
    asm volatile(
        "mma.sync.aligned.m16n8k16.row.col.f32.bf16.bf16.f32 "
        "{%0,%1,%2,%3},{%4,%5,%6,%7},{%8,%9},{%0,%1,%2,%3};"
        : "+f"(d[0]), "+f"(d[1]), "+f"(d[2]), "+f"(d[3])
        : "r"(a[0]), "r"(a[1]), "r"(a[2]), "r"(a[3]), "r"(b[0]), "r"(b[1]));
}
__device__ __forceinline__ void cp16(uint32_t s, const void* g) {
    asm volatile("cp.async.cg.shared.global [%0], [%1], 16;" :: "r"(s), "l"(g));
}
__device__ __forceinline__ void cp_commit() {
    asm volatile("cp.async.commit_group;" ::: "memory");
}
__device__ __forceinline__ void cp_wait0() {
    asm volatile("cp.async.wait_group 0;" ::: "memory");
}
__device__ __forceinline__ uint32_t pack_bf2(__nv_bfloat16 a, __nv_bfloat16 b) {
    return (uint32_t)__bfloat16_as_ushort(a) |
           ((uint32_t)__bfloat16_as_ushort(b) << 16);
}
__device__ __forceinline__ void split_pack(float x, float y,
                                           uint32_t& hi, uint32_t& lo) {
    const __nv_bfloat16 hx = __float2bfloat16(x);
    const __nv_bfloat16 hy = __float2bfloat16(y);
    hi = pack_bf2(hx, hy);
    lo = pack_bf2(__float2bfloat16(x - __bfloat162float(hx)),
                  __float2bfloat16(y - __bfloat162float(hy)));
}

// ---------------------------------------------------------------------------
// Fused prep: x split + both weight transpose/splits in one launch.
// ---------------------------------------------------------------------------
#define NBLK_X  ((B_SZ * SEQ * CH) / (256 * 4))      /* 6144 */
#define NBLK_WQ ((QKV_LD / 32) * (CH / 32))          /* 1728 */
#define NBLK_WP ((CH / 32) * (CH / 32))              /* 576  */

__device__ __forceinline__ void transpose_split_body(
    const float* __restrict__ W, __nv_bfloat16* __restrict__ Th,
    __nv_bfloat16* __restrict__ Tl, int K, int Nn, int bx, int by, int tid)
{
    __shared__ float tile[32][33];
    const int n0 = bx * 32;
    const int k0 = by * 32;
    const int tx = tid & 31;
    const int ty = tid >> 5;
    for (int i = ty; i < 32; i += 8)
        tile[i][tx] = W[(size_t)(k0 + i) * Nn + n0 + tx];
    __syncthreads();
    for (int i = ty; i < 32; i += 8) {
        const float v = tile[tx][i];
        const __nv_bfloat16 h = __float2bfloat16(v);
        const __nv_bfloat16 l = __float2bfloat16(v - __bfloat162float(h));
        const size_t o = (size_t)(n0 + i) * K + k0 + tx;
        Th[o] = h;
        Tl[o] = l;
    }
}

__global__ __launch_bounds__(256) void prep_kernel(
    const float* __restrict__ X,
    const float* __restrict__ Wq, const float* __restrict__ Wp)
{
    const int bid = blockIdx.x;
    if (bid < NBLK_X) {
        const size_t i = ((size_t)bid * 256 + threadIdx.x) * 4;
        const float4 v = *(const float4*)(X + i);
        uint32_t h0, l0, h1, l1;
        split_pack(v.x, v.y, h0, l0);
        split_pack(v.z, v.w, h1, l1);
        *(uint2*)(g_xh + i) = make_uint2(h0, h1);
        *(uint2*)(g_xl + i) = make_uint2(l0, l1);
    } else if (bid < NBLK_X + NBLK_WQ) {
        const int tb = bid - NBLK_X;
        transpose_split_body(Wq, g_wqh, g_wql, CH, QKV_LD,
                             tb % (QKV_LD / 32), tb / (QKV_LD / 32),
                             threadIdx.x);
    } else {
        const int tb = bid - NBLK_X - NBLK_WQ;
        transpose_split_body(Wp, g_wph, g_wpl, CH, CH,
                             tb % (CH / 32), tb / (CH / 32),
                             threadIdx.x);
    }
}

// ---------------------------------------------------------------------------
// All-bf16 split GEMM: CTA 128x128, 8 warps (4m x 2n), warp tile 32x64,
// BK=32, 2-stage cp.async (best-measured configuration).
// ---------------------------------------------------------------------------
#define LDA 40
#define ARR_BYTES (128 * LDA * 2)
#define STAGE_BYTES (4 * ARR_BYTES)
#define GEMM_SMEM (2 * STAGE_BYTES)

__global__ __launch_bounds__(256) void gemm_bf16_kernel(
    const __nv_bfloat16* __restrict__ Ah, const __nv_bfloat16* __restrict__ Al,
    const __nv_bfloat16* __restrict__ Bh, const __nv_bfloat16* __restrict__ Bl,
    const float* __restrict__ bias, float* __restrict__ C,
    __nv_bfloat16* __restrict__ Chi, __nv_bfloat16* __restrict__ Clo,
    int M, int Nn, int K, int has_bias, int qcols)
{
    extern __shared__ __align__(16) char dsm[];
    const uint32_t sbase = smem_u32(dsm);

    const int tid  = threadIdx.x;
    const int wid  = tid >> 5;
    const int lane = tid & 31;
    const int wr   = wid >> 1;
    const int wc   = wid & 1;
    const int bm   = blockIdx.y * 128;
    const int bn   = blockIdx.x * 128;

    const int r    = tid >> 1;
    const int half = tid & 1;
    const __nv_bfloat16* gAh = Ah + (size_t)(bm + r) * K + half * 16;
    const __nv_bfloat16* gAl = Al + (size_t)(bm + r) * K + half * 16;
    const __nv_bfloat16* gBh = Bh + (size_t)(bn + r) * K + half * 16;
    const __nv_bfloat16* gBl = Bl + (size_t)(bn + r) * K + half * 16;
    const uint32_t sOff = (uint32_t)(r * LDA + half * 16) * 2;

    const int lrow = lane & 15;
    const int lcol = (lane >> 4) << 3;

    float acc[2][8][4];
#pragma unroll
    for (int a = 0; a < 2; a++)
#pragma unroll
        for (int b = 0; b < 8; b++)
#pragma unroll
            for (int j = 0; j < 4; j++) acc[a][b][j] = 0.f;

    const int NIT = K / 32;

    {
        cp16(sbase + sOff,      gAh);  cp16(sbase + sOff + 16,      gAh + 8);
        cp16(sbase + ARR_BYTES + sOff,      gAl);
        cp16(sbase + ARR_BYTES + sOff + 16, gAl + 8);
        cp16(sbase + 2 * ARR_BYTES + sOff,      gBh);
        cp16(sbase + 2 * ARR_BYTES + sOff + 16, gBh + 8);
        cp16(sbase + 3 * ARR_BYTES + sOff,      gBl);
        cp16(sbase + 3 * ARR_BYTES + sOff + 16, gBl + 8);
        cp_commit();
    }

    for (int it = 0; it < NIT; it++) {
        cp_wait0();
        __syncthreads();

        if (it + 1 < NIT) {
            const int k0 = (it + 1) * 32;
            const uint32_t us = sbase + ((it + 1) & 1) * STAGE_BYTES;
            cp16(us + sOff,      gAh + k0);  cp16(us + sOff + 16,      gAh + k0 + 8);
            cp16(us + ARR_BYTES + sOff,      gAl + k0);
            cp16(us + ARR_BYTES + sOff + 16, gAl + k0 + 8);
            cp16(us + 2 * ARR_BYTES + sOff,      gBh + k0);
            cp16(us + 2 * ARR_BYTES + sOff + 16, gBh + k0 + 8);
            cp16(us + 3 * ARR_BYTES + sOff,      gBl + k0);
            cp16(us + 3 * ARR_BYTES + sOff + 16, gBl + k0 + 8);
            cp_commit();
        }

        const uint32_t uS  = sbase + (it & 1) * STAGE_BYTES;
        const uint32_t uAh = uS;
        const uint32_t uAl = uS + ARR_BYTES;
        const uint32_t uBh = uS + 2 * ARR_BYTES;
        const uint32_t uBl = uS + 3 * ARR_BYTES;

#pragma unroll
        for (int kk = 0; kk < 2; kk++) {
            const uint32_t cByte = (uint32_t)((kk * 16 + lcol) * 2);
            uint32_t ah[2][4], al[2][4];
#pragma unroll
            for (int a = 0; a < 2; a++) {
                const uint32_t ro =
                    (uint32_t)((wr * 32 + a * 16 + lrow) * (LDA * 2)) + cByte;
                ldmatrix_x4(ah[a], uAh + ro);
                ldmatrix_x4(al[a], uAl + ro);
            }
            uint32_t bh[8][2], bl[8][2];
#pragma unroll
            for (int g = 0; g < 4; g++) {
                uint32_t t[4];
                const uint32_t ro =
                    (uint32_t)((wc * 64 + g * 16 + lrow) * (LDA * 2)) + cByte;
                ldmatrix_x4(t, uBh + ro);
                bh[g * 2][0] = t[0]; bh[g * 2][1] = t[2];
                bh[g * 2 + 1][0] = t[1]; bh[g * 2 + 1][1] = t[3];
                ldmatrix_x4(t, uBl + ro);
                bl[g * 2][0] = t[0]; bl[g * 2][1] = t[2];
                bl[g * 2 + 1][0] = t[1]; bl[g * 2 + 1][1] = t[3];
            }
#pragma unroll
            for (int a = 0; a < 2; a++)
#pragma unroll
                for (int b = 0; b < 8; b++) {
                    mma_bf16(acc[a][b], ah[a], bh[b]);
                    mma_bf16(acc[a][b], ah[a], bl[b]);
                    mma_bf16(acc[a][b], al[a], bh[b]);
                }
        }
        __syncthreads();
    }

    const int g  = lane >> 2;
    const int t2 = (lane & 3) * 2;
#pragma unroll
    for (int a = 0; a < 2; a++) {
        const int row0 = bm + wr * 32 + a * 16 + g;
#pragma unroll
        for (int b = 0; b < 8; b++) {
            const int col = bn + wc * 64 + b * 8 + t2;
            if (Chi) {
                const float sc = (col < qcols) ? ATT_SCALE : 1.f;
                uint32_t h0, l0, h1, l1;
                split_pack(acc[a][b][0] * sc, acc[a][b][1] * sc, h0, l0);
                split_pack(acc[a][b][2] * sc, acc[a][b][3] * sc, h1, l1);
                const size_t o0 = (size_t)row0 * Nn + col;
                const size_t o1 = (size_t)(row0 + 8) * Nn + col;
                *(uint32_t*)(Chi + o0) = h0;
                *(uint32_t*)(Clo + o0) = l0;
                *(uint32_t*)(Chi + o1) = h1;
                *(uint32_t*)(Clo + o1) = l1;
            } else {
                float bx = 0.f, by = 0.f;
                if (has_bias) { bx = bias[col]; by = bias[col + 1]; }
                *(float2*)(C + (size_t)row0 * Nn + col) =
                    make_float2(acc[a][b][0] + bx, acc[a][b][1] + by);
                *(float2*)(C + (size_t)(row0 + 8) * Nn + col) =
                    make_float2(acc[a][b][2] + bx, acc[a][b][3] + by);
            }
        }
    }
}

// ---------------------------------------------------------------------------
// Flash attention (R14/R15 version)
// ---------------------------------------------------------------------------
#define KLD 72
#define FARR_BYTES (128 * KLD * 2)
#define FSTG_BYTES (4 * FARR_BYTES)
#define FLASH_SMEM (2 * FSTG_BYTES)

__global__ __launch_bounds__(256, 1) void flash_mma_kernel()
{
    extern __shared__ __align__(16) char fsm[];
    const uint32_t sbase = smem_u32(fsm);

    const int tid  = threadIdx.x;
    const int wid  = tid >> 5;
    const int lane = tid & 31;
    const int lrow = lane & 15;
    const int lcol = (lane >> 4) << 3;
    const int q0 = blockIdx.x * 128;
    const int b  = blockIdx.y / NHEAD;
    const int h  = blockIdx.y % NHEAD;

    const size_t tokbase = (size_t)b * SEQ;
    const __nv_bfloat16* qh_g = g_qh + tokbase * QKV_LD + h * HDIM;
    const __nv_bfloat16* ql_g = g_ql + tokbase * QKV_LD + h * HDIM;
    const __nv_bfloat16* kh_g = qh_g + CH;
    const __nv_bfloat16* kl_g = ql_g + CH;
    const __nv_bfloat16* vh_g = qh_g + 2 * CH;
    const __nv_bfloat16* vl_g = ql_g + 2 * CH;

    {
        __nv_bfloat16* Kh1 = (__nv_bfloat16*)(fsm + FSTG_BYTES);
        __nv_bfloat16* Kl1 = (__nv_bfloat16*)(fsm + FSTG_BYTES + FARR_BYTES);
        const int ldr = tid >> 1;
        const int ldh = (tid & 1) * 32;
        const __nv_bfloat16* sh = qh_g + (size_t)(q0 + ldr) * QKV_LD + ldh;
        const __nv_bfloat16* sl = ql_g + (size_t)(q0 + ldr) * QKV_LD + ldh;
#pragma unroll
        for (int i = 0; i < 4; i++) {
            *(uint4*)&Kh1[ldr * KLD + ldh + i * 8] = *(const uint4*)(sh + i * 8);
            *(uint4*)&Kl1[ldr * KLD + ldh + i * 8] = *(const uint4*)(sl + i * 8);
        }
    }
    __syncthreads();

    {
        const __nv_bfloat16* gsrc[4] = { kh_g, kl_g, vh_g, vl_g };
#pragma unroll
        for (int arr = 0; arr < 4; arr++)
#pragma unroll
            for (int c = 0; c < 4; c++) {
                const int ch  = tid + c * 256;
                const int row = ch >> 3;
                const int col = ch & 7;
                cp16(sbase + arr * FARR_BYTES + (uint32_t)(row * KLD + col * 8) * 2,
                     gsrc[arr] + (size_t)row * QKV_LD + col * 8);
            }
        cp_commit();
    }

    uint32_t qfh[4][4], qfl[4][4];
    {
        const uint32_t uQh = sbase + FSTG_BYTES;
        const uint32_t uQl = uQh + FARR_BYTES;
#pragma unroll
        for (int ks = 0; ks < 4; ks++) {
            const uint32_t ro =
                (uint32_t)((wid * 16 + lrow) * (KLD * 2)) + (ks * 16 + lcol) * 2;
            ldmatrix_x4(qfh[ks], uQh + ro);
            ldmatrix_x4(qfl[ks], uQl + ro);
        }
    }

    float m0 = -1e30f, m1 = -1e30f, l0 = 0.f, l1 = 0.f;
    float oacc[8][4];
#pragma unroll
    for (int j = 0; j < 8; j++)
#pragma unroll
        for (int c = 0; c < 4; c++) oacc[j][c] = 0.f;

    for (int t = 0; t < SEQ / 128; t++) {
        const int s = t & 1;
        cp_wait0();
        __syncthreads();

        if (t + 1 < SEQ / 128) {
            const int jn = (t + 1) * 128;
            const uint32_t us = sbase + (s ^ 1) * FSTG_BYTES;
            const __nv_bfloat16* gsrc[4] = { kh_g, kl_g, vh_g, vl_g };
#pragma unroll
            for (int arr = 0; arr < 4; arr++)
#pragma unroll
                for (int c = 0; c < 4; c++) {
                    const int ch  = tid + c * 256;
                    const int row = ch >> 3;
                    const int col = ch & 7;
                    cp16(us + arr * FARR_BYTES + (uint32_t)(row * KLD + col * 8) * 2,
                         gsrc[arr] + (size_t)(jn + row) * QKV_LD + col * 8);
                }
            cp_commit();
        }

        const uint32_t uS  = sbase + s * FSTG_BYTES;
        const uint32_t uKh = uS;
        const uint32_t uKl = uS + FARR_BYTES;
        const uint32_t uVh = uS + 2 * FARR_BYTES;
        const uint32_t uVl = uS + 3 * FARR_BYTES;

        float sacc[16][4];
#pragma unroll
        for (int j = 0; j < 16; j++)
#pragma unroll
            for (int c = 0; c < 4; c++) sacc[j][c] = 0.f;

#pragma unroll
        for (int ks = 0; ks < 4; ks++) {
            const uint32_t cByte = (uint32_t)((ks * 16 + lcol) * 2);
#pragma unroll
            for (int ng = 0; ng < 4; ng++) {
                uint32_t bh[4][2], bl[4][2], tt[4];
#pragma unroll
                for (int h2 = 0; h2 < 2; h2++) {
                    const uint32_t ro =
                        (uint32_t)((ng * 32 + h2 * 16 + lrow) * (KLD * 2)) + cByte;
                    ldmatrix_x4(tt, uKh + ro);
                    bh[h2 * 2][0] = tt[0]; bh[h2 * 2][1] = tt[2];
                    bh[h2 * 2 + 1][0] = tt[1]; bh[h2 * 2 + 1][1] = tt[3];
                    ldmatrix_x4(tt, uKl + ro);
                    bl[h2 * 2][0] = tt[0]; bl[h2 * 2][1] = tt[2];
                    bl[h2 * 2 + 1][0] = tt[1]; bl[h2 * 2 + 1][1] = tt[3];
                }
#pragma unroll
                for (int f = 0; f < 4; f++) {
                    float* d = sacc[ng * 4 + f];
                    mma_bf16(d, qfh[ks], bh[f]);
                    mma_bf16(d, qfh[ks], bl[f]);
                    mma_bf16(d, qfl[ks], bh[f]);
                }
            }
        }

        float mx0 = sacc[0][0], mx1 = sacc[0][2];
#pragma unroll
        for (int j = 0; j < 16; j++) {
            mx0 = fmaxf(mx0, fmaxf(sacc[j][0], sacc[j][1]));
            mx1 = fmaxf(mx1, fmaxf(sacc[j][2], sacc[j][3]));
        }
        mx0 = fmaxf(mx0, __shfl_xor_sync(0xffffffffu, mx0, 1));
        mx0 = fmaxf(mx0, __shfl_xor_sync(0xffffffffu, mx0, 2));
        mx1 = fmaxf(mx1, __shfl_xor_sync(0xffffffffu, mx1, 1));
        mx1 = fmaxf(mx1, __shfl_xor_sync(0xffffffffu, mx1, 2));

        const float mn0 = fmaxf(m0, mx0);
        const float mn1 = fmaxf(m1, mx1);
        const float cr0 = __expf(m0 - mn0);
        const float cr1 = __expf(m1 - mn1);
        m0 = mn0; m1 = mn1;

#pragma unroll
        for (int j = 0; j < 8; j++) {
            oacc[j][0] *= cr0; oacc[j][1] *= cr0;
            oacc[j][2] *= cr1; oacc[j][3] *= cr1;
        }

        float ps0 = 0.f, ps1 = 0.f;
#pragma unroll
        for (int ks = 0; ks < 8; ks++) {
#pragma unroll
            for (int jj = 0; jj < 2; jj++) {
                const int j = 2 * ks + jj;
                sacc[j][0] = __expf(sacc[j][0] - mn0);
                sacc[j][1] = __expf(sacc[j][1] - mn0);
                sacc[j][2] = __expf(sacc[j][2] - mn1);
                sacc[j][3] = __expf(sacc[j][3] - mn1);
                ps0 += sacc[j][0] + sacc[j][1];
                ps1 += sacc[j][2] + sacc[j][3];
            }

            uint32_t pah[4], pal[4];
            split_pack(sacc[2 * ks][0], sacc[2 * ks][1], pah[0], pal[0]);
            split_pack(sacc[2 * ks][2], sacc[2 * ks][3], pah[1], pal[1]);
            split_pack(sacc[2 * ks + 1][0], sacc[2 * ks + 1][1], pah[2], pal[2]);
            split_pack(sacc[2 * ks + 1][2], sacc[2 * ks + 1][3], pah[3], pal[3]);

#pragma unroll
            for (int nd = 0; nd < 4; nd++) {
                const uint32_t ro =
                    (uint32_t)((ks * 16 + lrow) * (KLD * 2)) +
                    (uint32_t)((nd * 16 + lcol) * 2);
                uint32_t th[4], tl[4];
                ldmatrix_x4_trans(th, uVh + ro);
                ldmatrix_x4_trans(tl, uVl + ro);
#pragma unroll
                for (int f = 0; f < 2; f++) {
                    float* d = oacc[nd * 2 + f];
                    uint32_t vh2[2] = { th[f * 2], th[f * 2 + 1] };
                    uint32_t vl2[2] = { tl[f * 2], tl[f * 2 + 1] };
                    mma_bf16(d, pah, vh2);
                    mma_bf16(d, pah, vl2);
                    mma_bf16(d, pal, vh2);
                }
            }
        }

        ps0 += __shfl_xor_sync(0xffffffffu, ps0, 1);
        ps0 += __shfl_xor_sync(0xffffffffu, ps0, 2);
        ps1 += __shfl_xor_sync(0xffffffffu, ps1, 1);
        ps1 += __shfl_xor_sync(0xffffffffu, ps1, 2);
        l0 = l0 * cr0 + ps0;
        l1 = l1 * cr1 + ps1;
    }

    const int g  = lane >> 2;
    const int t2 = (lane & 3) * 2;
    const float inv0 = 1.f / l0;
    const float inv1 = 1.f / l1;
    const int row0 = q0 + wid * 16 + g;
    __nv_bfloat16* oh = g_ath + (tokbase + row0) * CH + h * HDIM;
    __nv_bfloat16* ol = g_atl + (tokbase + row0) * CH + h * HDIM;
#pragma unroll
    for (int j = 0; j < 8; j++) {
        uint32_t hh, ll;
        split_pack(oacc[j][0] * inv0, oacc[j][1] * inv0, hh, ll);
        *(uint32_t*)(oh + j * 8 + t2) = hh;
        *(uint32_t*)(ol + j * 8 + t2) = ll;
        split_pack(oacc[j][2] * inv1, oacc[j][3] * inv1, hh, ll);
        *(uint32_t*)(oh + 8 * (size_t)CH + j * 8 + t2) = hh;
        *(uint32_t*)(ol + 8 * (size_t)CH + j * 8 + t2) = ll;
    }
}

// ---------------------------------------------------------------------------
extern "C" void kernel_launch(void* const* d_in, const int* in_sizes, int n_in,
                              void* d_out, int out_size)
{
    const float* x      = (const float*)d_in[0];
    const float* w_qkv  = (const float*)d_in[1];
    const float* w_proj = (const float*)d_in[2];
    const float* b_proj = (const float*)d_in[3];
    float* out = (float*)d_out;

    __nv_bfloat16 *xh, *xl, *qh, *ql, *ath, *atl, *wqh, *wql, *wph, *wpl;
    cudaGetSymbolAddress((void**)&xh, g_xh);
    cudaGetSymbolAddress((void**)&xl, g_xl);
    cudaGetSymbolAddress((void**)&qh, g_qh);
    cudaGetSymbolAddress((void**)&ql, g_ql);
    cudaGetSymbolAddress((void**)&ath, g_ath);
    cudaGetSymbolAddress((void**)&atl, g_atl);
    cudaGetSymbolAddress((void**)&wqh, g_wqh);
    cudaGetSymbolAddress((void**)&wql, g_wql);
    cudaGetSymbolAddress((void**)&wph, g_wph);
    cudaGetSymbolAddress((void**)&wpl, g_wpl);

    // 0) Fused prep (one launch)
    prep_kernel<<<NBLK_X + NBLK_WQ + NBLK_WP, 256>>>(x, w_qkv, w_proj);

    // 1) QKV projection: 128-wide N tiles, grid (18,64)
    cudaFuncSetAttribute(gemm_bf16_kernel,
                         cudaFuncAttributeMaxDynamicSharedMemorySize, GEMM_SMEM);
    gemm_bf16_kernel<<<dim3(QKV_LD / 128, (B_SZ * SEQ) / 128), 256, GEMM_SMEM>>>(
        xh, xl, wqh, wql, nullptr, nullptr, qh, ql,
        B_SZ * SEQ, QKV_LD, CH, 0, CH);

    // 2) Flash attention
    cudaFuncSetAttribute(flash_mma_kernel,
                         cudaFuncAttributeMaxDynamicSharedMemorySize, FLASH_SMEM);
    flash_mma_kernel<<<dim3(SEQ / 128, B_SZ * NHEAD), 256, FLASH_SMEM>>>();

    // 3) Output projection: 128-wide N tiles, grid (6,64)
    gemm_bf16_kernel<<<dim3(CH / 128, (B_SZ * SEQ) / 128), 256, GEMM_SMEM>>>(
        ath, atl, wph, wpl, b_proj, out, nullptr, nullptr,
        B_SZ * SEQ, CH, CH, 1, 0);
}